// round 13
// baseline (speedup 1.0000x reference)
#include <cuda_runtime.h>
#include <cuda_fp16.h>

// SmileMoENorm — single-kernel version: R6's main kernel (the measured HBM
// floor: 155us @ 83% DRAM) with the fp16 pack pass FUSED in, eliminating
// the separate k_pack graph node (+launch) that cost ~4us of the 159us total.
//
// Blocks 0..31 pack 256 (gamma,beta) pairs each into d_pk and bump d_ready;
// all blocks acquire-poll d_ready==32 after their row-load+stats (table is
// published well before any first-wave warp reaches the poll). A completion
// counter makes the LAST block reset d_ready/d_done, so every launch starts
// and ends in the identical state — deterministic, no cross-call caching.
// Deadlock-free: packers are wave-1 and depend on nothing; reset requires
// all blocks' post-wait __syncthreads() to have passed.

#define N_TOKENS    131072
#define HIDDEN      1024
#define NUM_EXPERTS 8
#define H4          (HIDDEN / 4)
#define EPS         1e-5f
#define GRID_BLOCKS (N_TOKENS / 8)      // 16384, 8 warps/block
#define PACK_BLOCKS 32                  // 32 x 256 threads = 8192 elements

__device__ __half2  d_pk[NUM_EXPERTS * HIDDEN];  // (gamma, beta) per element
__device__ unsigned d_ready;                     // packer blocks completed
__device__ unsigned d_done;                      // blocks finished (for reset)

__global__ __launch_bounds__(256, 4)
void smile_moe_norm_kernel(const float4* __restrict__ x,
                           const float4* __restrict__ logits4,   // [N,2] float4
                           const float* __restrict__ gamma,
                           const float* __restrict__ beta,
                           float4* __restrict__ out) {
    const int tid           = threadIdx.x;
    const int warp_in_block = tid >> 5;
    const int lane          = tid & 31;
    const int token         = blockIdx.x * 8 + warp_in_block;

    // ---- fused pack pass (blocks 0..31, one element per thread) ------------
    if (blockIdx.x < PACK_BLOCKS) {
        const int i = blockIdx.x * 256 + tid;            // 0..8191
        d_pk[i] = __floats2half2_rn(gamma[i], beta[i]);
        __threadfence();                                 // publish d_pk
        __syncthreads();                                 // whole block's writes
        if (tid == 0) atomicAdd(&d_ready, 1u);           // release via RMW
    }

    // ---- router: top-2 of 8 logits, renormalized softmax weights ----------
    const float4 la = __ldg(&logits4[token * 2 + 0]);
    const float4 lb = __ldg(&logits4[token * 2 + 1]);
    float l[NUM_EXPERTS] = { la.x, la.y, la.z, la.w, lb.x, lb.y, lb.z, lb.w };

    float best = l[0], second = -3.4e38f;
    int   e0 = 0,     e1 = 0;
    #pragma unroll
    for (int i = 1; i < NUM_EXPERTS; i++) {
        float v = l[i];
        if (v > best)        { second = best; e1 = e0; best = v; e0 = i; }
        else if (v > second) { second = v; e1 = i; }
    }
    const float t  = __expf(second - best);     // full-softmax denom cancels
    const float w0 = 1.0f / (1.0f + t);
    const float w1 = 1.0f - w0;
    const __half2 w0h = __float2half2_rn(w0);
    const __half2 w1h = __float2half2_rn(w1);

    // ---- pass over row: registers + warp reduction (streaming loads) -------
    const float4* xr = x + (size_t)token * H4;
    float4 v[8];
    float sum = 0.0f, sq = 0.0f;
    #pragma unroll
    for (int k = 0; k < 8; k++) {
        v[k] = __ldcs(&xr[lane + 32 * k]);      // touch-once: evict-first
        sum += v[k].x + v[k].y + v[k].z + v[k].w;
        sq = fmaf(v[k].x, v[k].x, sq); sq = fmaf(v[k].y, v[k].y, sq);
        sq = fmaf(v[k].z, v[k].z, sq); sq = fmaf(v[k].w, v[k].w, sq);
    }
    #pragma unroll
    for (int off = 16; off > 0; off >>= 1) {
        sum += __shfl_xor_sync(0xFFFFFFFFu, sum, off);
        sq  += __shfl_xor_sync(0xFFFFFFFFu, sq,  off);
    }
    const float mean = sum * (1.0f / HIDDEN);
    const float var  = fmaf(-mean, mean, sq * (1.0f / HIDDEN));
    const float rstd = rsqrtf(var + EPS);
    const float mr   = -mean * rstd;            // normed = x*rstd + mr

    // ---- wait for d_pk (published ~immediately; latency hidden by stats) ---
    {
        unsigned r;
        while (true) {
            asm volatile("ld.acquire.gpu.global.u32 %0, [%1];"
                         : "=r"(r) : "l"(&d_ready));
            if (r >= PACK_BLOCKS) break;
            __nanosleep(64);
        }
    }

    // ---- epilogue: packed-fp16 blended affine + streaming store -------------
    const __half2* pk0 = d_pk + e0 * HIDDEN;
    const __half2* pk1 = d_pk + e1 * HIDDEN;
    float4* orow = out + (size_t)token * H4;

    #pragma unroll
    for (int k = 0; k < 8; k++) {
        const int h4 = lane + 32 * k;           // float4 index
        const int h  = 4 * h4;                  // element index
        const uint4 r0 = *(const uint4*)(pk0 + h);
        const uint4 r1 = *(const uint4*)(pk1 + h);

        const float nx = fmaf(v[k].x, rstd, mr);
        const float ny = fmaf(v[k].y, rstd, mr);
        const float nz = fmaf(v[k].z, rstd, mr);
        const float nw = fmaf(v[k].w, rstd, mr);

        __half2 a, b; float2 fb; float4 o;
        a = *(const __half2*)&r0.x; b = *(const __half2*)&r1.x;
        fb = __half22float2(__hfma2(a, w0h, __hmul2(b, w1h)));
        o.x = fmaf(nx, fb.x, fb.y);

        a = *(const __half2*)&r0.y; b = *(const __half2*)&r1.y;
        fb = __half22float2(__hfma2(a, w0h, __hmul2(b, w1h)));
        o.y = fmaf(ny, fb.x, fb.y);

        a = *(const __half2*)&r0.z; b = *(const __half2*)&r1.z;
        fb = __half22float2(__hfma2(a, w0h, __hmul2(b, w1h)));
        o.z = fmaf(nz, fb.x, fb.y);

        a = *(const __half2*)&r0.w; b = *(const __half2*)&r1.w;
        fb = __half22float2(__hfma2(a, w0h, __hmul2(b, w1h)));
        o.w = fmaf(nw, fb.x, fb.y);

        __stcs(&orow[h4], o);                   // streaming store
    }

    // ---- completion + state reset (last block rewinds d_ready/d_done) ------
    __syncthreads();   // all warps of this block are past the d_ready wait
    if (tid == 0) {
        const unsigned old = atomicAdd(&d_done, 1u);
        if (old == GRID_BLOCKS - 1) {            // every block fully past wait
            d_done = 0;
            asm volatile("st.relaxed.gpu.global.u32 [%0], %1;"
                         :: "l"(&d_ready), "r"(0u) : "memory");
        }
    }
}

// ------------------------------------------------------------------ launch
extern "C" void kernel_launch(void* const* d_in, const int* in_sizes, int n_in,
                              void* d_out, int out_size) {
    const float4* x       = (const float4*)d_in[0];  // hidden_states [N, H]
    const float4* logits4 = (const float4*)d_in[1];  // router_logits [N, 8]
    const float*  gamma   = (const float*)d_in[2];   // [E, H]
    const float*  beta    = (const float*)d_in[3];   // [E, H]
    float4* out           = (float4*)d_out;

    smile_moe_norm_kernel<<<GRID_BLOCKS, 256>>>(x, logits4, gamma, beta, out);
}

// round 14
// speedup vs baseline: 1.1661x; 1.1661x over previous
#include <cuda_runtime.h>
#include <cuda_fp16.h>

// SmileMoENorm — FINAL (exact R6/R12 configuration; measured 159.0/159.1 us).
//
// 13 rounds established this as the floor:
//  - Mandatory traffic: 1.023 GB (x read + f32 out write + logits). Main
//    kernel moves it at 6.6 TB/s = the ~6300 B/cyc full-chip LTS cap
//    (path-independent: R11's TMA bulk variant confirmed).
//  - fp16-packed (gamma,beta) table minimized ancillary bytes (R4: -13%,
//    rel_err 3.3e-4 << 1e-3 gate).
//  - All perturbations regressed: +occupancy (R5/R8), 256-bit accesses (R7),
//    2-token pipeline (R10), pair-sort (R2), smem staging (R3), TMA bulk
//    (R11), single-kernel fusion with spin-wait (R13: polls on one L2 line
//    serialize at LTS).
//  - The ~4us two-node overhead is fixed graph cost (R9, R13 both failed to
//    compress it).
//
// Structure: one warp per token; full row single-read into v[8] (.cs);
// top-2 routing in-warp (softmax denominator cancels -> sigmoid);
// fp16-packed affine table built by k_pack, overlapped via PDL; .cs stores.

#define N_TOKENS    131072
#define HIDDEN      1024
#define NUM_EXPERTS 8
#define H4          (HIDDEN / 4)
#define EPS         1e-5f

__device__ __half2 d_pk[NUM_EXPERTS * HIDDEN];   // (gamma, beta) per element

// ---- pre-pass: pack gamma/beta into fp16 ----------------------------------
__global__ void k_pack(const float* __restrict__ gamma,
                       const float* __restrict__ beta) {
    const int i = blockIdx.x * blockDim.x + threadIdx.x;   // 0..8191
    d_pk[i] = __floats2half2_rn(gamma[i], beta[i]);
}

// ------------------------------------------------------------- main kernel
__global__ __launch_bounds__(256, 4)
void smile_moe_norm_kernel(const float4* __restrict__ x,
                           const float4* __restrict__ logits4,   // [N,2] float4
                           float4* __restrict__ out) {
    const int warp_in_block = threadIdx.x >> 5;
    const int lane          = threadIdx.x & 31;
    const int token         = blockIdx.x * (blockDim.x >> 5) + warp_in_block;

    // ---- router: top-2 of 8 logits, renormalized softmax weights ----------
    const float4 la = __ldg(&logits4[token * 2 + 0]);
    const float4 lb = __ldg(&logits4[token * 2 + 1]);
    float l[NUM_EXPERTS] = { la.x, la.y, la.z, la.w, lb.x, lb.y, lb.z, lb.w };

    float best = l[0], second = -3.4e38f;
    int   e0 = 0,     e1 = 0;
    #pragma unroll
    for (int i = 1; i < NUM_EXPERTS; i++) {
        float v = l[i];
        if (v > best)        { second = best; e1 = e0; best = v; e0 = i; }
        else if (v > second) { second = v; e1 = i; }
    }
    const float t  = __expf(second - best);     // full-softmax denom cancels
    const float w0 = 1.0f / (1.0f + t);
    const float w1 = 1.0f - w0;
    const __half2 w0h = __float2half2_rn(w0);
    const __half2 w1h = __float2half2_rn(w1);

    // ---- pass over row: registers + warp reduction (streaming loads) -------
    const float4* xr = x + (size_t)token * H4;
    float4 v[8];
    float sum = 0.0f, sq = 0.0f;
    #pragma unroll
    for (int k = 0; k < 8; k++) {
        v[k] = __ldcs(&xr[lane + 32 * k]);      // touch-once: evict-first
        sum += v[k].x + v[k].y + v[k].z + v[k].w;
        sq = fmaf(v[k].x, v[k].x, sq); sq = fmaf(v[k].y, v[k].y, sq);
        sq = fmaf(v[k].z, v[k].z, sq); sq = fmaf(v[k].w, v[k].w, sq);
    }
    #pragma unroll
    for (int off = 16; off > 0; off >>= 1) {
        sum += __shfl_xor_sync(0xFFFFFFFFu, sum, off);
        sq  += __shfl_xor_sync(0xFFFFFFFFu, sq,  off);
    }
    const float mean = sum * (1.0f / HIDDEN);
    const float var  = fmaf(-mean, mean, sq * (1.0f / HIDDEN));
    const float rstd = rsqrtf(var + EPS);
    const float mr   = -mean * rstd;            // normed = x*rstd + mr

    // PDL: d_pk is written by k_pack; wait for it only now (hidden latency).
    cudaGridDependencySynchronize();

    // ---- epilogue: packed-fp16 blended affine + streaming store -------------
    const __half2* pk0 = d_pk + e0 * HIDDEN;
    const __half2* pk1 = d_pk + e1 * HIDDEN;
    float4* orow = out + (size_t)token * H4;

    #pragma unroll
    for (int k = 0; k < 8; k++) {
        const int h4 = lane + 32 * k;           // float4 index
        const int h  = 4 * h4;                  // element index
        const uint4 r0 = *(const uint4*)(pk0 + h);
        const uint4 r1 = *(const uint4*)(pk1 + h);

        const float nx = fmaf(v[k].x, rstd, mr);
        const float ny = fmaf(v[k].y, rstd, mr);
        const float nz = fmaf(v[k].z, rstd, mr);
        const float nw = fmaf(v[k].w, rstd, mr);

        __half2 a, b; float2 fb; float4 o;
        a = *(const __half2*)&r0.x; b = *(const __half2*)&r1.x;
        fb = __half22float2(__hfma2(a, w0h, __hmul2(b, w1h)));
        o.x = fmaf(nx, fb.x, fb.y);

        a = *(const __half2*)&r0.y; b = *(const __half2*)&r1.y;
        fb = __half22float2(__hfma2(a, w0h, __hmul2(b, w1h)));
        o.y = fmaf(ny, fb.x, fb.y);

        a = *(const __half2*)&r0.z; b = *(const __half2*)&r1.z;
        fb = __half22float2(__hfma2(a, w0h, __hmul2(b, w1h)));
        o.z = fmaf(nz, fb.x, fb.y);

        a = *(const __half2*)&r0.w; b = *(const __half2*)&r1.w;
        fb = __half22float2(__hfma2(a, w0h, __hmul2(b, w1h)));
        o.w = fmaf(nw, fb.x, fb.y);

        __stcs(&orow[h4], o);                   // streaming store
    }
}

// ------------------------------------------------------------------ launch
extern "C" void kernel_launch(void* const* d_in, const int* in_sizes, int n_in,
                              void* d_out, int out_size) {
    const float4* x       = (const float4*)d_in[0];  // hidden_states [N, H]
    const float4* logits4 = (const float4*)d_in[1];  // router_logits [N, 8]
    const float*  gamma   = (const float*)d_in[2];   // [E, H]
    const float*  beta    = (const float*)d_in[3];   // [E, H]
    float4* out           = (float4*)d_out;

    k_pack<<<(NUM_EXPERTS * HIDDEN) / 256, 256>>>(gamma, beta);

    // Main kernel with programmatic dependent launch: overlaps with k_pack;
    // the in-kernel cudaGridDependencySynchronize() provides the ordering.
    cudaLaunchConfig_t cfg = {};
    cfg.gridDim  = dim3(N_TOKENS / 8, 1, 1);         // 8 warps/block
    cfg.blockDim = dim3(256, 1, 1);
    cudaLaunchAttribute attr[1];
    attr[0].id = cudaLaunchAttributeProgrammaticStreamSerialization;
    attr[0].val.programmaticStreamSerializationAllowed = 1;
    cfg.attrs = attr;
    cfg.numAttrs = 1;
    cudaLaunchKernelEx(&cfg, smile_moe_norm_kernel, x, logits4, out);
}

// round 15
// speedup vs baseline: 1.1687x; 1.0022x over previous
#include <cuda_runtime.h>
#include <cuda_fp16.h>

// SmileMoENorm — FINAL (exact R6/R12 configuration; measured 159.0 / 159.1 /
// 160.5 us across three identical runs — run-to-run noise band +-1.5us).
//
// 14 rounds established this as the floor:
//  - Mandatory traffic: 1.023 GB (x read + f32 out write + logits). Main
//    kernel moves it at ~6.6 TB/s = the ~6300 B/cyc full-chip LTS cap
//    (path-independent: R11's TMA bulk variant, identical traffic, slower).
//  - fp16-packed (gamma,beta) table minimized ancillary bytes (R4: -13%,
//    rel_err 3.3e-4 << 1e-3 gate; fp8 would breach the gate).
//  - All perturbations regressed: +occupancy (R5/R8), 256-bit accesses (R7),
//    2-token pipeline (R10), pair-sort (R2), smem staging (R3), TMA bulk
//    (R11), single-kernel fusion with spin-wait (R13: single-line acquire
//    polls serialize at LTS).
//  - ~4us two-node overhead is fixed graph cost (R9/R13 failed to compress).
//
// Structure: one warp per token; full row single-read into v[8] (.cs);
// top-2 routing in-warp (softmax denominator cancels -> sigmoid);
// fp16-packed affine table built by k_pack, overlapped via PDL; .cs stores.

#define N_TOKENS    131072
#define HIDDEN      1024
#define NUM_EXPERTS 8
#define H4          (HIDDEN / 4)
#define EPS         1e-5f

__device__ __half2 d_pk[NUM_EXPERTS * HIDDEN];   // (gamma, beta) per element

// ---- pre-pass: pack gamma/beta into fp16 ----------------------------------
__global__ void k_pack(const float* __restrict__ gamma,
                       const float* __restrict__ beta) {
    const int i = blockIdx.x * blockDim.x + threadIdx.x;   // 0..8191
    d_pk[i] = __floats2half2_rn(gamma[i], beta[i]);
}

// ------------------------------------------------------------- main kernel
__global__ __launch_bounds__(256, 4)
void smile_moe_norm_kernel(const float4* __restrict__ x,
                           const float4* __restrict__ logits4,   // [N,2] float4
                           float4* __restrict__ out) {
    const int warp_in_block = threadIdx.x >> 5;
    const int lane          = threadIdx.x & 31;
    const int token         = blockIdx.x * (blockDim.x >> 5) + warp_in_block;

    // ---- router: top-2 of 8 logits, renormalized softmax weights ----------
    const float4 la = __ldg(&logits4[token * 2 + 0]);
    const float4 lb = __ldg(&logits4[token * 2 + 1]);
    float l[NUM_EXPERTS] = { la.x, la.y, la.z, la.w, lb.x, lb.y, lb.z, lb.w };

    float best = l[0], second = -3.4e38f;
    int   e0 = 0,     e1 = 0;
    #pragma unroll
    for (int i = 1; i < NUM_EXPERTS; i++) {
        float v = l[i];
        if (v > best)        { second = best; e1 = e0; best = v; e0 = i; }
        else if (v > second) { second = v; e1 = i; }
    }
    const float t  = __expf(second - best);     // full-softmax denom cancels
    const float w0 = 1.0f / (1.0f + t);
    const float w1 = 1.0f - w0;
    const __half2 w0h = __float2half2_rn(w0);
    const __half2 w1h = __float2half2_rn(w1);

    // ---- pass over row: registers + warp reduction (streaming loads) -------
    const float4* xr = x + (size_t)token * H4;
    float4 v[8];
    float sum = 0.0f, sq = 0.0f;
    #pragma unroll
    for (int k = 0; k < 8; k++) {
        v[k] = __ldcs(&xr[lane + 32 * k]);      // touch-once: evict-first
        sum += v[k].x + v[k].y + v[k].z + v[k].w;
        sq = fmaf(v[k].x, v[k].x, sq); sq = fmaf(v[k].y, v[k].y, sq);
        sq = fmaf(v[k].z, v[k].z, sq); sq = fmaf(v[k].w, v[k].w, sq);
    }
    #pragma unroll
    for (int off = 16; off > 0; off >>= 1) {
        sum += __shfl_xor_sync(0xFFFFFFFFu, sum, off);
        sq  += __shfl_xor_sync(0xFFFFFFFFu, sq,  off);
    }
    const float mean = sum * (1.0f / HIDDEN);
    const float var  = fmaf(-mean, mean, sq * (1.0f / HIDDEN));
    const float rstd = rsqrtf(var + EPS);
    const float mr   = -mean * rstd;            // normed = x*rstd + mr

    // PDL: d_pk is written by k_pack; wait for it only now (hidden latency).
    cudaGridDependencySynchronize();

    // ---- epilogue: packed-fp16 blended affine + streaming store -------------
    const __half2* pk0 = d_pk + e0 * HIDDEN;
    const __half2* pk1 = d_pk + e1 * HIDDEN;
    float4* orow = out + (size_t)token * H4;

    #pragma unroll
    for (int k = 0; k < 8; k++) {
        const int h4 = lane + 32 * k;           // float4 index
        const int h  = 4 * h4;                  // element index
        const uint4 r0 = *(const uint4*)(pk0 + h);
        const uint4 r1 = *(const uint4*)(pk1 + h);

        const float nx = fmaf(v[k].x, rstd, mr);
        const float ny = fmaf(v[k].y, rstd, mr);
        const float nz = fmaf(v[k].z, rstd, mr);
        const float nw = fmaf(v[k].w, rstd, mr);

        __half2 a, b; float2 fb; float4 o;
        a = *(const __half2*)&r0.x; b = *(const __half2*)&r1.x;
        fb = __half22float2(__hfma2(a, w0h, __hmul2(b, w1h)));
        o.x = fmaf(nx, fb.x, fb.y);

        a = *(const __half2*)&r0.y; b = *(const __half2*)&r1.y;
        fb = __half22float2(__hfma2(a, w0h, __hmul2(b, w1h)));
        o.y = fmaf(ny, fb.x, fb.y);

        a = *(const __half2*)&r0.z; b = *(const __half2*)&r1.z;
        fb = __half22float2(__hfma2(a, w0h, __hmul2(b, w1h)));
        o.z = fmaf(nz, fb.x, fb.y);

        a = *(const __half2*)&r0.w; b = *(const __half2*)&r1.w;
        fb = __half22float2(__hfma2(a, w0h, __hmul2(b, w1h)));
        o.w = fmaf(nw, fb.x, fb.y);

        __stcs(&orow[h4], o);                   // streaming store
    }
}

// ------------------------------------------------------------------ launch
extern "C" void kernel_launch(void* const* d_in, const int* in_sizes, int n_in,
                              void* d_out, int out_size) {
    const float4* x       = (const float4*)d_in[0];  // hidden_states [N, H]
    const float4* logits4 = (const float4*)d_in[1];  // router_logits [N, 8]
    const float*  gamma   = (const float*)d_in[2];   // [E, H]
    const float*  beta    = (const float*)d_in[3];   // [E, H]
    float4* out           = (float4*)d_out;

    k_pack<<<(NUM_EXPERTS * HIDDEN) / 256, 256>>>(gamma, beta);

    // Main kernel with programmatic dependent launch: overlaps with k_pack;
    // the in-kernel cudaGridDependencySynchronize() provides the ordering.
    cudaLaunchConfig_t cfg = {};
    cfg.gridDim  = dim3(N_TOKENS / 8, 1, 1);         // 8 warps/block
    cfg.blockDim = dim3(256, 1, 1);
    cudaLaunchAttribute attr[1];
    attr[0].id = cudaLaunchAttributeProgrammaticStreamSerialization;
    attr[0].val.programmaticStreamSerializationAllowed = 1;
    cfg.attrs = attr;
    cfg.numAttrs = 1;
    cudaLaunchKernelEx(&cfg, smile_moe_norm_kernel, x, logits4, out);
}

// round 16
// speedup vs baseline: 1.1712x; 1.0022x over previous
#include <cuda_runtime.h>
#include <cuda_fp16.h>

// SmileMoENorm — FINAL (exact R6/R12 configuration).
// Measured across four identical runs: 159.0 / 159.1 / 160.5 / 160.1 us
// (main kernel 154.7-156.4 us @ DRAM 82.5-83.5%) — stable at the roofline.
//
// Why this is the floor (15 rounds of evidence):
//  - Mandatory traffic: 1.023 GB (x read 512MB + f32 out write 512MB +
//    logits 4MB). Moves at ~6.6 TB/s; L2 only ~39% busy -> binder is HBM
//    mixed read/write efficiency itself, uncontrollable from SASS:
//    direction-batching (R11 TMA bulk), request-rate (R5/R8 occupancy),
//    width (R7 256-bit), and phase-interleave (R10) all regressed.
//  - Bytes minimized: fp16-packed (gamma,beta) table (R4: -13% traffic,
//    rel_err 3.3e-4 << 1e-3; fp8 would breach the gate).
//  - Structure optimal: one warp/token, full row single-read into v[8];
//    pair-sort (R2), smem staging (R3), fusion+spin-wait (R13) all worse.
//  - ~4us two-node overhead is fixed graph cost (R9/R13 failed to shrink).

#define N_TOKENS    131072
#define HIDDEN      1024
#define NUM_EXPERTS 8
#define H4          (HIDDEN / 4)
#define EPS         1e-5f

__device__ __half2 d_pk[NUM_EXPERTS * HIDDEN];   // (gamma, beta) per element

// ---- pre-pass: pack gamma/beta into fp16 ----------------------------------
__global__ void k_pack(const float* __restrict__ gamma,
                       const float* __restrict__ beta) {
    const int i = blockIdx.x * blockDim.x + threadIdx.x;   // 0..8191
    d_pk[i] = __floats2half2_rn(gamma[i], beta[i]);
}

// ------------------------------------------------------------- main kernel
__global__ __launch_bounds__(256, 4)
void smile_moe_norm_kernel(const float4* __restrict__ x,
                           const float4* __restrict__ logits4,   // [N,2] float4
                           float4* __restrict__ out) {
    const int warp_in_block = threadIdx.x >> 5;
    const int lane          = threadIdx.x & 31;
    const int token         = blockIdx.x * (blockDim.x >> 5) + warp_in_block;

    // ---- router: top-2 of 8 logits, renormalized softmax weights ----------
    const float4 la = __ldg(&logits4[token * 2 + 0]);
    const float4 lb = __ldg(&logits4[token * 2 + 1]);
    float l[NUM_EXPERTS] = { la.x, la.y, la.z, la.w, lb.x, lb.y, lb.z, lb.w };

    float best = l[0], second = -3.4e38f;
    int   e0 = 0,     e1 = 0;
    #pragma unroll
    for (int i = 1; i < NUM_EXPERTS; i++) {
        float v = l[i];
        if (v > best)        { second = best; e1 = e0; best = v; e0 = i; }
        else if (v > second) { second = v; e1 = i; }
    }
    const float t  = __expf(second - best);     // full-softmax denom cancels
    const float w0 = 1.0f / (1.0f + t);
    const float w1 = 1.0f - w0;
    const __half2 w0h = __float2half2_rn(w0);
    const __half2 w1h = __float2half2_rn(w1);

    // ---- pass over row: registers + warp reduction (streaming loads) -------
    const float4* xr = x + (size_t)token * H4;
    float4 v[8];
    float sum = 0.0f, sq = 0.0f;
    #pragma unroll
    for (int k = 0; k < 8; k++) {
        v[k] = __ldcs(&xr[lane + 32 * k]);      // touch-once: evict-first
        sum += v[k].x + v[k].y + v[k].z + v[k].w;
        sq = fmaf(v[k].x, v[k].x, sq); sq = fmaf(v[k].y, v[k].y, sq);
        sq = fmaf(v[k].z, v[k].z, sq); sq = fmaf(v[k].w, v[k].w, sq);
    }
    #pragma unroll
    for (int off = 16; off > 0; off >>= 1) {
        sum += __shfl_xor_sync(0xFFFFFFFFu, sum, off);
        sq  += __shfl_xor_sync(0xFFFFFFFFu, sq,  off);
    }
    const float mean = sum * (1.0f / HIDDEN);
    const float var  = fmaf(-mean, mean, sq * (1.0f / HIDDEN));
    const float rstd = rsqrtf(var + EPS);
    const float mr   = -mean * rstd;            // normed = x*rstd + mr

    // PDL: d_pk is written by k_pack; wait for it only now (hidden latency).
    cudaGridDependencySynchronize();

    // ---- epilogue: packed-fp16 blended affine + streaming store -------------
    const __half2* pk0 = d_pk + e0 * HIDDEN;
    const __half2* pk1 = d_pk + e1 * HIDDEN;
    float4* orow = out + (size_t)token * H4;

    #pragma unroll
    for (int k = 0; k < 8; k++) {
        const int h4 = lane + 32 * k;           // float4 index
        const int h  = 4 * h4;                  // element index
        const uint4 r0 = *(const uint4*)(pk0 + h);
        const uint4 r1 = *(const uint4*)(pk1 + h);

        const float nx = fmaf(v[k].x, rstd, mr);
        const float ny = fmaf(v[k].y, rstd, mr);
        const float nz = fmaf(v[k].z, rstd, mr);
        const float nw = fmaf(v[k].w, rstd, mr);

        __half2 a, b; float2 fb; float4 o;
        a = *(const __half2*)&r0.x; b = *(const __half2*)&r1.x;
        fb = __half22float2(__hfma2(a, w0h, __hmul2(b, w1h)));
        o.x = fmaf(nx, fb.x, fb.y);

        a = *(const __half2*)&r0.y; b = *(const __half2*)&r1.y;
        fb = __half22float2(__hfma2(a, w0h, __hmul2(b, w1h)));
        o.y = fmaf(ny, fb.x, fb.y);

        a = *(const __half2*)&r0.z; b = *(const __half2*)&r1.z;
        fb = __half22float2(__hfma2(a, w0h, __hmul2(b, w1h)));
        o.z = fmaf(nz, fb.x, fb.y);

        a = *(const __half2*)&r0.w; b = *(const __half2*)&r1.w;
        fb = __half22float2(__hfma2(a, w0h, __hmul2(b, w1h)));
        o.w = fmaf(nw, fb.x, fb.y);

        __stcs(&orow[h4], o);                   // streaming store
    }
}

// ------------------------------------------------------------------ launch
extern "C" void kernel_launch(void* const* d_in, const int* in_sizes, int n_in,
                              void* d_out, int out_size) {
    const float4* x       = (const float4*)d_in[0];  // hidden_states [N, H]
    const float4* logits4 = (const float4*)d_in[1];  // router_logits [N, 8]
    const float*  gamma   = (const float*)d_in[2];   // [E, H]
    const float*  beta    = (const float*)d_in[3];   // [E, H]
    float4* out           = (float4*)d_out;

    k_pack<<<(NUM_EXPERTS * HIDDEN) / 256, 256>>>(gamma, beta);

    // Main kernel with programmatic dependent launch: overlaps with k_pack;
    // the in-kernel cudaGridDependencySynchronize() provides the ordering.
    cudaLaunchConfig_t cfg = {};
    cfg.gridDim  = dim3(N_TOKENS / 8, 1, 1);         // 8 warps/block
    cfg.blockDim = dim3(256, 1, 1);
    cudaLaunchAttribute attr[1];
    attr[0].id = cudaLaunchAttributeProgrammaticStreamSerialization;
    attr[0].val.programmaticStreamSerializationAllowed = 1;
    cfg.attrs = attr;
    cfg.numAttrs = 1;
    cudaLaunchKernelEx(&cfg, smile_moe_norm_kernel, x, logits4, out);
}

// round 17
// speedup vs baseline: 1.1745x; 1.0028x over previous
#include <cuda_runtime.h>
#include <cuda_fp16.h>

// SmileMoENorm — FINAL (converged configuration, 5 replications:
// 159.0 / 159.1 / 160.5 / 160.1 / 159.8 us; main kernel 154.7-156.4 us
// at DRAM 82.5-83.5% — stationary at the HBM mixed-stream roofline).
//
// Evidence ledger (16 rounds):
//  - Mandatory traffic 1.023 GB (x read + f32 out + logits) at ~6.6 TB/s;
//    L2 only ~39% busy -> binder is HBM read/write-mix efficiency itself,
//    not LTS, not request rate: TMA bulk (R11), occupancy (R5/R8), 256-bit
//    (R7), phase-interleave (R10) all regressed identically-sized traffic.
//  - Ancillary bytes minimized: fp16-packed (gamma,beta) table (R4, -13%,
//    rel_err 3.3e-4 << 1e-3 gate; fp8 would breach it).
//  - Structure optimal: one warp/token, full-row single-read into v[8];
//    pair-sort (R2), smem staging (R3), fusion+spin-wait (R13) all worse.
//  - ~4us two-node overhead is fixed graph cost (R9/R13 could not shrink).

#define N_TOKENS    131072
#define HIDDEN      1024
#define NUM_EXPERTS 8
#define H4          (HIDDEN / 4)
#define EPS         1e-5f

__device__ __half2 d_pk[NUM_EXPERTS * HIDDEN];   // (gamma, beta) per element

// ---- pre-pass: pack gamma/beta into fp16 ----------------------------------
__global__ void k_pack(const float* __restrict__ gamma,
                       const float* __restrict__ beta) {
    const int i = blockIdx.x * blockDim.x + threadIdx.x;   // 0..8191
    d_pk[i] = __floats2half2_rn(gamma[i], beta[i]);
}

// ------------------------------------------------------------- main kernel
__global__ __launch_bounds__(256, 4)
void smile_moe_norm_kernel(const float4* __restrict__ x,
                           const float4* __restrict__ logits4,   // [N,2] float4
                           float4* __restrict__ out) {
    const int warp_in_block = threadIdx.x >> 5;
    const int lane          = threadIdx.x & 31;
    const int token         = blockIdx.x * (blockDim.x >> 5) + warp_in_block;

    // ---- router: top-2 of 8 logits, renormalized softmax weights ----------
    const float4 la = __ldg(&logits4[token * 2 + 0]);
    const float4 lb = __ldg(&logits4[token * 2 + 1]);
    float l[NUM_EXPERTS] = { la.x, la.y, la.z, la.w, lb.x, lb.y, lb.z, lb.w };

    float best = l[0], second = -3.4e38f;
    int   e0 = 0,     e1 = 0;
    #pragma unroll
    for (int i = 1; i < NUM_EXPERTS; i++) {
        float v = l[i];
        if (v > best)        { second = best; e1 = e0; best = v; e0 = i; }
        else if (v > second) { second = v; e1 = i; }
    }
    const float t  = __expf(second - best);     // full-softmax denom cancels
    const float w0 = 1.0f / (1.0f + t);
    const float w1 = 1.0f - w0;
    const __half2 w0h = __float2half2_rn(w0);
    const __half2 w1h = __float2half2_rn(w1);

    // ---- pass over row: registers + warp reduction (streaming loads) -------
    const float4* xr = x + (size_t)token * H4;
    float4 v[8];
    float sum = 0.0f, sq = 0.0f;
    #pragma unroll
    for (int k = 0; k < 8; k++) {
        v[k] = __ldcs(&xr[lane + 32 * k]);      // touch-once: evict-first
        sum += v[k].x + v[k].y + v[k].z + v[k].w;
        sq = fmaf(v[k].x, v[k].x, sq); sq = fmaf(v[k].y, v[k].y, sq);
        sq = fmaf(v[k].z, v[k].z, sq); sq = fmaf(v[k].w, v[k].w, sq);
    }
    #pragma unroll
    for (int off = 16; off > 0; off >>= 1) {
        sum += __shfl_xor_sync(0xFFFFFFFFu, sum, off);
        sq  += __shfl_xor_sync(0xFFFFFFFFu, sq,  off);
    }
    const float mean = sum * (1.0f / HIDDEN);
    const float var  = fmaf(-mean, mean, sq * (1.0f / HIDDEN));
    const float rstd = rsqrtf(var + EPS);
    const float mr   = -mean * rstd;            // normed = x*rstd + mr

    // PDL: d_pk is written by k_pack; wait for it only now (hidden latency).
    cudaGridDependencySynchronize();

    // ---- epilogue: packed-fp16 blended affine + streaming store -------------
    const __half2* pk0 = d_pk + e0 * HIDDEN;
    const __half2* pk1 = d_pk + e1 * HIDDEN;
    float4* orow = out + (size_t)token * H4;

    #pragma unroll
    for (int k = 0; k < 8; k++) {
        const int h4 = lane + 32 * k;           // float4 index
        const int h  = 4 * h4;                  // element index
        const uint4 r0 = *(const uint4*)(pk0 + h);
        const uint4 r1 = *(const uint4*)(pk1 + h);

        const float nx = fmaf(v[k].x, rstd, mr);
        const float ny = fmaf(v[k].y, rstd, mr);
        const float nz = fmaf(v[k].z, rstd, mr);
        const float nw = fmaf(v[k].w, rstd, mr);

        __half2 a, b; float2 fb; float4 o;
        a = *(const __half2*)&r0.x; b = *(const __half2*)&r1.x;
        fb = __half22float2(__hfma2(a, w0h, __hmul2(b, w1h)));
        o.x = fmaf(nx, fb.x, fb.y);

        a = *(const __half2*)&r0.y; b = *(const __half2*)&r1.y;
        fb = __half22float2(__hfma2(a, w0h, __hmul2(b, w1h)));
        o.y = fmaf(ny, fb.x, fb.y);

        a = *(const __half2*)&r0.z; b = *(const __half2*)&r1.z;
        fb = __half22float2(__hfma2(a, w0h, __hmul2(b, w1h)));
        o.z = fmaf(nz, fb.x, fb.y);

        a = *(const __half2*)&r0.w; b = *(const __half2*)&r1.w;
        fb = __half22float2(__hfma2(a, w0h, __hmul2(b, w1h)));
        o.w = fmaf(nw, fb.x, fb.y);

        __stcs(&orow[h4], o);                   // streaming store
    }
}

// ------------------------------------------------------------------ launch
extern "C" void kernel_launch(void* const* d_in, const int* in_sizes, int n_in,
                              void* d_out, int out_size) {
    const float4* x       = (const float4*)d_in[0];  // hidden_states [N, H]
    const float4* logits4 = (const float4*)d_in[1];  // router_logits [N, 8]
    const float*  gamma   = (const float*)d_in[2];   // [E, H]
    const float*  beta    = (const float*)d_in[3];   // [E, H]
    float4* out           = (float4*)d_out;

    k_pack<<<(NUM_EXPERTS * HIDDEN) / 256, 256>>>(gamma, beta);

    // Main kernel with programmatic dependent launch: overlaps with k_pack;
    // the in-kernel cudaGridDependencySynchronize() provides the ordering.
    cudaLaunchConfig_t cfg = {};
    cfg.gridDim  = dim3(N_TOKENS / 8, 1, 1);         // 8 warps/block
    cfg.blockDim = dim3(256, 1, 1);
    cudaLaunchAttribute attr[1];
    attr[0].id = cudaLaunchAttributeProgrammaticStreamSerialization;
    attr[0].val.programmaticStreamSerializationAllowed = 1;
    cfg.attrs = attr;
    cfg.numAttrs = 1;
    cudaLaunchKernelEx(&cfg, smile_moe_norm_kernel, x, logits4, out);
}